// round 6
// baseline (speedup 1.0000x reference)
#include <cuda_runtime.h>
#include <math.h>

// Problem constants
#define TS   1024
#define BS   64
#define HID  512
#define G4   2048
#define NCTA 128
#define NGRP 64                        // CTAs per barrier group (one per b-half)
#define LTHREADS 512
#define MROWS 65536                    // T*B rows of the projection GEMM
#define TBH  ((size_t)TS * BS * HID)   // 33554432
#define BH   (BS * HID)                // 32768
// smem: h tile [32][516] + W_hh slice [8 j][stride 2068] (bank-padded)
#define H_STRIDE 516
#define WJ_STRIDE 2068
#define WG_STRIDE 516
#define LSTM_SMEM ((32 * H_STRIDE + 8 * WJ_STRIDE) * 4)   // 132224 bytes

// Scratch (device globals: the sanctioned allocation-free path)
__device__ float g_xgates[(size_t)G4 * MROWS];     // 512 MB, TRANSPOSED [col][row]
__device__ float g_out1[(size_t)TS * BS * HID];    // 128 MB: layer-0 output sequence
__device__ float g_hbuf[2][BH];                    // double-buffered hidden state
__device__ unsigned int g_barG[2];                 // per-group barrier counters

// ---- packed f32x2 helpers (sm_100+ PTX) -----------------------------------
__device__ __forceinline__ unsigned long long fma2(unsigned long long a,
                                                   unsigned long long b,
                                                   unsigned long long c) {
    unsigned long long d;
    asm("fma.rn.f32x2 %0, %1, %2, %3;" : "=l"(d) : "l"(a), "l"(b), "l"(c));
    return d;
}
__device__ __forceinline__ unsigned long long pack2(float x, float y) {
    unsigned long long d;
    asm("mov.b64 %0, {%1, %2};" : "=l"(d) : "f"(x), "f"(y));
    return d;
}
__device__ __forceinline__ float2 unpack2(unsigned long long v) {
    float2 r;
    asm("mov.b64 {%0, %1}, %2;" : "=f"(r.x), "=f"(r.y) : "l"(v));
    return r;
}

// ---- release/acquire barrier primitives (no MEMBAR.GL on critical path) ----
__device__ __forceinline__ void red_release_add(unsigned int* p, unsigned int v) {
    asm volatile("red.release.gpu.global.add.u32 [%0], %1;" :: "l"(p), "r"(v) : "memory");
}
__device__ __forceinline__ unsigned int ld_acquire(const unsigned int* p) {
    unsigned int v;
    asm volatile("ld.acquire.gpu.global.u32 %0, [%1];" : "=r"(v) : "l"(p) : "memory");
    return v;
}

// ---------------------------------------------------------------------------
// Input projection GEMM: C_T[g][m] = sum_k A[m,k] * W[g,k] + b1[g] + b2[g]
// Tile 128x128x16, 256 threads, 8x8 per thread, FFMA2 inner product.
// Output stored TRANSPOSED so the recurrence reads coalesced in batch.
// Also resets the recurrence barrier counters (runs before each lstm pass).
// ---------------------------------------------------------------------------
__global__ __launch_bounds__(256, 2) void gemm_xg(
    const float* __restrict__ A,
    const float* __restrict__ W,
    const float* __restrict__ b1,
    const float* __restrict__ b2)
{
    if (blockIdx.x == 0 && blockIdx.y == 0 && threadIdx.x == 0) {
        g_barG[0] = 0u;
        g_barG[1] = 0u;
    }

    __shared__ float As[16][128];
    __shared__ float Bs[16][128];
    const int tid = threadIdx.x;
    const int m0 = blockIdx.y * 128;
    const int n0 = blockIdx.x * 128;
    const int tx = tid & 15, ty = tid >> 4;
    const int lr = tid >> 2;
    const int lk = (tid & 3) << 2;

    const float* Ap = A + (size_t)(m0 + lr) * HID + lk;
    const float* Wp = W + (size_t)(n0 + lr) * HID + lk;

    unsigned long long acc2[8][4];
#pragma unroll
    for (int i = 0; i < 8; i++)
#pragma unroll
        for (int j = 0; j < 4; j++) acc2[i][j] = 0ull;

    for (int k0 = 0; k0 < HID; k0 += 16) {
        float4 a0 = *(const float4*)(Ap + k0);
        float4 a1 = *(const float4*)(Ap + (size_t)64 * HID + k0);
        float4 w0 = *(const float4*)(Wp + k0);
        float4 w1 = *(const float4*)(Wp + (size_t)64 * HID + k0);
        __syncthreads();
        As[lk + 0][lr] = a0.x; As[lk + 1][lr] = a0.y; As[lk + 2][lr] = a0.z; As[lk + 3][lr] = a0.w;
        As[lk + 0][lr + 64] = a1.x; As[lk + 1][lr + 64] = a1.y; As[lk + 2][lr + 64] = a1.z; As[lk + 3][lr + 64] = a1.w;
        Bs[lk + 0][lr] = w0.x; Bs[lk + 1][lr] = w0.y; Bs[lk + 2][lr] = w0.z; Bs[lk + 3][lr] = w0.w;
        Bs[lk + 0][lr + 64] = w1.x; Bs[lk + 1][lr + 64] = w1.y; Bs[lk + 2][lr + 64] = w1.z; Bs[lk + 3][lr + 64] = w1.w;
        __syncthreads();
#pragma unroll
        for (int k = 0; k < 16; k++) {
            float a[8];
            *(float4*)&a[0] = *(const float4*)&As[k][ty * 8];
            *(float4*)&a[4] = *(const float4*)&As[k][ty * 8 + 4];
            const ulonglong2* bp = (const ulonglong2*)&Bs[k][tx * 8];
            ulonglong2 t0 = bp[0];
            ulonglong2 t1 = bp[1];
#pragma unroll
            for (int i = 0; i < 8; i++) {
                unsigned long long ad = pack2(a[i], a[i]);
                acc2[i][0] = fma2(ad, t0.x, acc2[i][0]);
                acc2[i][1] = fma2(ad, t0.y, acc2[i][1]);
                acc2[i][2] = fma2(ad, t1.x, acc2[i][2]);
                acc2[i][3] = fma2(ad, t1.y, acc2[i][3]);
            }
        }
    }

    float val[8][8];
#pragma unroll
    for (int i = 0; i < 8; i++)
#pragma unroll
        for (int jp = 0; jp < 4; jp++) {
            float2 p = unpack2(acc2[i][jp]);
            val[i][2 * jp] = p.x;
            val[i][2 * jp + 1] = p.y;
        }
#pragma unroll
    for (int u = 0; u < 8; u++) {
        int col = n0 + tx * 8 + u;
        float bias = b1[col] + b2[col];
        float* Cp = g_xgates + (size_t)col * MROWS + m0 + ty * 8;
        float4 lo, hi;
        lo.x = val[0][u] + bias; lo.y = val[1][u] + bias;
        lo.z = val[2][u] + bias; lo.w = val[3][u] + bias;
        hi.x = val[4][u] + bias; hi.y = val[5][u] + bias;
        hi.z = val[6][u] + bias; hi.w = val[7][u] + bias;
        *(float4*)Cp = lo;
        *(float4*)(Cp + 4) = hi;
    }
}

// ---------------------------------------------------------------------------
// Persistent recurrence. 128 CTAs x 512 threads (k-split: 2 threads per cell,
// interleaved 16B k-chunks, combined with one shfl.bfly per gate).
// 16 warps/SM = 4/SMSP for latency hiding. W_hh in smem (loaded once),
// c in register. Two-group release/acquire grid barrier per step.
// ---------------------------------------------------------------------------
__device__ __forceinline__ float sigmoidf_(float x) { return 1.f / (1.f + expf(-x)); }

__global__ __launch_bounds__(LTHREADS, 1) void lstm_kernel(
    const float* __restrict__ Whh,   // [4H][H] for this layer
    const float* __restrict__ h0,    // [B][H]
    const float* __restrict__ c0,    // [B][H]
    const float* __restrict__ xg,    // transposed gates [4H][T*B]
    float* __restrict__ out,         // [T][B][H]
    float* __restrict__ hn,          // [B][H]
    float* __restrict__ cn)          // [B][H]
{
    extern __shared__ float sm[];
    float* h_sm = sm;                        // [32][516]
    float* w_sm = sm + 32 * H_STRIDE;        // [8 j][4 g x 516] stride 2068

    const int tid  = threadIdx.x;
    const int cta  = blockIdx.x;
    const int jb   = cta & 63;       // 64 j-blocks of 8
    const int bb   = cta >> 6;       // 2 b-blocks of 32 -> barrier group
    const int warp = tid >> 5;
    const int lane = tid & 31;
    const int bq   = warp & 3;       // warp b-quad (0..3)
    const int jq   = warp >> 2;      // warp j-pair (0..3)
    const int bo   = lane & 7;       // lane b offset
    const int jp   = (lane >> 3) & 1;// lane j within pair
    const int kh   = lane >> 4;      // lane k-half (0/1) -> bfly 16 partner
    const int bl   = bq * 8 + bo;    // b_local 0..31
    const int jl   = jq * 2 + jp;    // j_local 0..7
    const int j    = jb * 8 + jl;
    const int b    = bb * 32 + bl;
    const int bj   = b * HID + j;

    unsigned int* bar = &g_barG[bb];

    // preload this CTA's W_hh slice: w_sm[jl][g][k], strides bank-padded
    {
        const float4* Wsrc = (const float4*)Whh;
#pragma unroll
        for (int idx = tid; idx < 4096; idx += LTHREADS) {   // float4 units
            int wjl = idx >> 9;
            int rem = idx & 511;
            int g   = rem >> 7;
            int k4  = rem & 127;
            *(float4*)&w_sm[wjl * WJ_STRIDE + g * WG_STRIDE + k4 * 4] =
                Wsrc[(((size_t)(g * HID + jb * 8 + wjl)) * HID >> 2) + k4];
        }
    }

    float c = c0[bj];
    if (kh == 0) __stcg(&g_hbuf[0][bj], h0[bj]);

    // per-gate xg base pointers (transposed layout: coalesced lane->b)
    const float* xi  = xg + (size_t)(0 * HID + j) * MROWS + b;
    const float* xf  = xg + (size_t)(1 * HID + j) * MROWS + b;
    const float* xgp = xg + (size_t)(2 * HID + j) * MROWS + b;
    const float* xo  = xg + (size_t)(3 * HID + j) * MROWS + b;

    // k-chunk interleave: thread kh handles chunks {2i + kh}, i = 0..63
    const ulonglong2* hp = (const ulonglong2*)&h_sm[bl * H_STRIDE] + kh;
    const ulonglong2* W0 = (const ulonglong2*)&w_sm[jl * WJ_STRIDE + 0 * WG_STRIDE] + kh;
    const ulonglong2* W1 = (const ulonglong2*)&w_sm[jl * WJ_STRIDE + 1 * WG_STRIDE] + kh;
    const ulonglong2* W2 = (const ulonglong2*)&w_sm[jl * WJ_STRIDE + 2 * WG_STRIDE] + kh;
    const ulonglong2* W3 = (const ulonglong2*)&w_sm[jl * WJ_STRIDE + 3 * WG_STRIDE] + kh;

    // initial barrier: h0 writes of this group visible before step 0
    unsigned expect = 0;
    __syncthreads();
    if (tid == 0) {
        red_release_add(bar, 1u);
        expect += NGRP;
        while (ld_acquire(bar) < expect) { }
    }
    __syncthreads();

    // prefetch step-0 gate biases
    float vxi = __ldg(xi), vxf = __ldg(xf), vxg = __ldg(xgp), vxo = __ldg(xo);

    float h = 0.f;
    for (int t = 0; t < TS; t++) {
        const float* hcur = g_hbuf[t & 1];
        // stage this group's 32-batch h slice into smem (L2, coalesced)
#pragma unroll
        for (int idx = tid; idx < 32 * 128; idx += LTHREADS) {
            int r  = idx >> 7;
            int c4 = idx & 127;
            float4 v = __ldcg((const float4*)(hcur + (size_t)(bb * 32 + r) * HID) + c4);
            *(float4*)&h_sm[r * H_STRIDE + c4 * 4] = v;
        }
        __syncthreads();

        unsigned long long ai2 = 0ull, af2 = 0ull, ag2 = 0ull, ao2 = 0ull;
#pragma unroll 8
        for (int i = 0; i < 64; i++) {
            ulonglong2 hv = hp[2 * i];
            ulonglong2 w0 = W0[2 * i], w1 = W1[2 * i], w2 = W2[2 * i], w3 = W3[2 * i];
            ai2 = fma2(hv.x, w0.x, ai2); ai2 = fma2(hv.y, w0.y, ai2);
            af2 = fma2(hv.x, w1.x, af2); af2 = fma2(hv.y, w1.y, af2);
            ag2 = fma2(hv.x, w2.x, ag2); ag2 = fma2(hv.y, w2.y, ag2);
            ao2 = fma2(hv.x, w3.x, ao2); ao2 = fma2(hv.y, w3.y, ao2);
        }

        float2 pi = unpack2(ai2); float2 pf = unpack2(af2);
        float2 pg = unpack2(ag2); float2 po = unpack2(ao2);
        float ri = pi.x + pi.y, rf = pf.x + pf.y;
        float rg = pg.x + pg.y, ro = po.x + po.y;
        // combine the two k-halves (partner lane = lane ^ 16)
        ri += __shfl_xor_sync(0xffffffffu, ri, 16);
        rf += __shfl_xor_sync(0xffffffffu, rf, 16);
        rg += __shfl_xor_sync(0xffffffffu, rg, 16);
        ro += __shfl_xor_sync(0xffffffffu, ro, 16);

        float ig = sigmoidf_(ri + vxi);
        float fg = sigmoidf_(rf + vxf);
        float gg = tanhf(rg + vxg);
        float og = sigmoidf_(ro + vxo);
        c = fg * c + ig * gg;
        h = og * tanhf(c);

        // publish h for step t+1, then arrive (release orders the stcg)
        if (kh == 0) __stcg(&g_hbuf[(t + 1) & 1][bj], h);
        __syncthreads();
        if (tid == 0) {
            red_release_add(bar, 1u);
            expect += NGRP;
        }

        // overlap with barrier wait: out[] DRAM store + next-step xg prefetch
        if (kh == 0) out[((size_t)t * BS + b) * HID + j] = h;
        if (t + 1 < TS) {
            int toff = (t + 1) * BS;
            vxi = __ldg(xi + toff);
            vxf = __ldg(xf + toff);
            vxg = __ldg(xgp + toff);
            vxo = __ldg(xo + toff);
        }

        if (tid == 0) {
            while (ld_acquire(bar) < expect) { }
        }
        __syncthreads();
    }

    if (kh == 0) {
        hn[bj] = h;
        cn[bj] = c;
    }
}

// ---------------------------------------------------------------------------
// Launch: per layer {gemm (resets barrier) -> persistent recurrence}.
// Output layout: [layer_out (T,B,H)][h_n (L,B,H)][c_n (L,B,H)]
// ---------------------------------------------------------------------------
extern "C" void kernel_launch(void* const* d_in, const int* in_sizes, int n_in,
                              void* d_out, int out_size)
{
    const float* x    = (const float*)d_in[0];
    const float* h0   = (const float*)d_in[1];
    const float* c0   = (const float*)d_in[2];
    const float* W_ih = (const float*)d_in[3];
    const float* W_hh = (const float*)d_in[4];
    const float* b_ih = (const float*)d_in[5];
    const float* b_hh = (const float*)d_in[6];
    float* out = (float*)d_out;

    cudaFuncSetAttribute(lstm_kernel, cudaFuncAttributeMaxDynamicSharedMemorySize, LSTM_SMEM);

    void* p_out1_v = nullptr;
    cudaGetSymbolAddress(&p_out1_v, g_out1);
    float* p_out1 = (float*)p_out1_v;
    void* p_xg_v = nullptr;
    cudaGetSymbolAddress(&p_xg_v, g_xgates);
    const float* p_xg = (const float*)p_xg_v;

    dim3 ggrid(G4 / 128, MROWS / 128);   // (16, 512)

    // Layer 0
    gemm_xg<<<ggrid, 256>>>(x, W_ih, b_ih, b_hh);
    lstm_kernel<<<NCTA, LTHREADS, LSTM_SMEM>>>(
        W_hh, h0, c0, p_xg,
        p_out1,
        out + TBH,                       // h_n[0]
        out + TBH + 2 * (size_t)BH);     // c_n[0]

    // Layer 1
    gemm_xg<<<ggrid, 256>>>(p_out1, W_ih + (size_t)G4 * HID, b_ih + G4, b_hh + G4);
    lstm_kernel<<<NCTA, LTHREADS, LSTM_SMEM>>>(
        W_hh + (size_t)G4 * HID, h0 + BH, c0 + BH, p_xg,
        out,                             // final layer_out
        out + TBH + (size_t)BH,          // h_n[1]
        out + TBH + 3 * (size_t)BH);     // c_n[1]

    (void)in_sizes; (void)n_in; (void)out_size;
}

// round 7
// speedup vs baseline: 1.0001x; 1.0001x over previous
#include <cuda_runtime.h>
#include <math.h>

// Problem constants
#define TS   1024
#define BS   64
#define HID  512
#define G4   2048
#define NCTA 128
#define NGRP 64                        // CTAs per barrier group (one per b-half)
#define LTHREADS 512
#define MROWS 65536                    // T*B rows of the projection GEMM
#define TBH  ((size_t)TS * BS * HID)   // 33554432
#define BH   (BS * HID)                // 32768
// smem: h tile [32][516] + W_hh slice [8 j][stride 2068] (bank-padded)
#define H_STRIDE 516
#define WJ_STRIDE 2068
#define WG_STRIDE 516
#define LSTM_SMEM ((32 * H_STRIDE + 8 * WJ_STRIDE) * 4)   // 132224 bytes

// Scratch (device globals: the sanctioned allocation-free path)
__device__ float g_xgates[(size_t)G4 * MROWS];     // 512 MB, TRANSPOSED [col][row]
__device__ float g_out1[(size_t)TS * BS * HID];    // 128 MB: layer-0 output sequence
__device__ float g_hbuf[2][BH];                    // double-buffered hidden state
__device__ unsigned int g_barG[2];                 // per-group barrier counters

// ---- packed f32x2 helpers (sm_100+ PTX) -----------------------------------
__device__ __forceinline__ unsigned long long fma2(unsigned long long a,
                                                   unsigned long long b,
                                                   unsigned long long c) {
    unsigned long long d;
    asm("fma.rn.f32x2 %0, %1, %2, %3;" : "=l"(d) : "l"(a), "l"(b), "l"(c));
    return d;
}
__device__ __forceinline__ unsigned long long pack2(float x, float y) {
    unsigned long long d;
    asm("mov.b64 %0, {%1, %2};" : "=l"(d) : "f"(x), "f"(y));
    return d;
}
__device__ __forceinline__ float2 unpack2(unsigned long long v) {
    float2 r;
    asm("mov.b64 {%0, %1}, %2;" : "=f"(r.x), "=f"(r.y) : "l"(v));
    return r;
}

// ---- release/acquire barrier primitives (no MEMBAR.GL on critical path) ----
__device__ __forceinline__ void red_release_add(unsigned int* p, unsigned int v) {
    asm volatile("red.release.gpu.global.add.u32 [%0], %1;" :: "l"(p), "r"(v) : "memory");
}
__device__ __forceinline__ unsigned int ld_acquire(const unsigned int* p) {
    unsigned int v;
    asm volatile("ld.acquire.gpu.global.u32 %0, [%1];" : "=r"(v) : "l"(p) : "memory");
    return v;
}

// ---------------------------------------------------------------------------
// Input projection GEMM: C_T[g][m] = sum_k A[m,k] * W[g,k] + b1[g] + b2[g]
// Tile 128x128x16, 256 threads, 8x8 per thread, FFMA2 inner product.
// Output stored TRANSPOSED so the recurrence reads coalesced in batch.
// Also resets the recurrence barrier counters (runs before each lstm pass).
// ---------------------------------------------------------------------------
__global__ __launch_bounds__(256, 2) void gemm_xg(
    const float* __restrict__ A,
    const float* __restrict__ W,
    const float* __restrict__ b1,
    const float* __restrict__ b2)
{
    if (blockIdx.x == 0 && blockIdx.y == 0 && threadIdx.x == 0) {
        g_barG[0] = 0u;
        g_barG[1] = 0u;
    }

    __shared__ float As[16][128];
    __shared__ float Bs[16][128];
    const int tid = threadIdx.x;
    const int m0 = blockIdx.y * 128;
    const int n0 = blockIdx.x * 128;
    const int tx = tid & 15, ty = tid >> 4;
    const int lr = tid >> 2;
    const int lk = (tid & 3) << 2;

    const float* Ap = A + (size_t)(m0 + lr) * HID + lk;
    const float* Wp = W + (size_t)(n0 + lr) * HID + lk;

    unsigned long long acc2[8][4];
#pragma unroll
    for (int i = 0; i < 8; i++)
#pragma unroll
        for (int j = 0; j < 4; j++) acc2[i][j] = 0ull;

    for (int k0 = 0; k0 < HID; k0 += 16) {
        float4 a0 = *(const float4*)(Ap + k0);
        float4 a1 = *(const float4*)(Ap + (size_t)64 * HID + k0);
        float4 w0 = *(const float4*)(Wp + k0);
        float4 w1 = *(const float4*)(Wp + (size_t)64 * HID + k0);
        __syncthreads();
        As[lk + 0][lr] = a0.x; As[lk + 1][lr] = a0.y; As[lk + 2][lr] = a0.z; As[lk + 3][lr] = a0.w;
        As[lk + 0][lr + 64] = a1.x; As[lk + 1][lr + 64] = a1.y; As[lk + 2][lr + 64] = a1.z; As[lk + 3][lr + 64] = a1.w;
        Bs[lk + 0][lr] = w0.x; Bs[lk + 1][lr] = w0.y; Bs[lk + 2][lr] = w0.z; Bs[lk + 3][lr] = w0.w;
        Bs[lk + 0][lr + 64] = w1.x; Bs[lk + 1][lr + 64] = w1.y; Bs[lk + 2][lr + 64] = w1.z; Bs[lk + 3][lr + 64] = w1.w;
        __syncthreads();
#pragma unroll
        for (int k = 0; k < 16; k++) {
            float a[8];
            *(float4*)&a[0] = *(const float4*)&As[k][ty * 8];
            *(float4*)&a[4] = *(const float4*)&As[k][ty * 8 + 4];
            const ulonglong2* bp = (const ulonglong2*)&Bs[k][tx * 8];
            ulonglong2 t0 = bp[0];
            ulonglong2 t1 = bp[1];
#pragma unroll
            for (int i = 0; i < 8; i++) {
                unsigned long long ad = pack2(a[i], a[i]);
                acc2[i][0] = fma2(ad, t0.x, acc2[i][0]);
                acc2[i][1] = fma2(ad, t0.y, acc2[i][1]);
                acc2[i][2] = fma2(ad, t1.x, acc2[i][2]);
                acc2[i][3] = fma2(ad, t1.y, acc2[i][3]);
            }
        }
    }

    float val[8][8];
#pragma unroll
    for (int i = 0; i < 8; i++)
#pragma unroll
        for (int jp = 0; jp < 4; jp++) {
            float2 p = unpack2(acc2[i][jp]);
            val[i][2 * jp] = p.x;
            val[i][2 * jp + 1] = p.y;
        }
#pragma unroll
    for (int u = 0; u < 8; u++) {
        int col = n0 + tx * 8 + u;
        float bias = b1[col] + b2[col];
        float* Cp = g_xgates + (size_t)col * MROWS + m0 + ty * 8;
        float4 lo, hi;
        lo.x = val[0][u] + bias; lo.y = val[1][u] + bias;
        lo.z = val[2][u] + bias; lo.w = val[3][u] + bias;
        hi.x = val[4][u] + bias; hi.y = val[5][u] + bias;
        hi.z = val[6][u] + bias; hi.w = val[7][u] + bias;
        *(float4*)Cp = lo;
        *(float4*)(Cp + 4) = hi;
    }
}

// ---------------------------------------------------------------------------
// Persistent recurrence. 128 CTAs x 512 threads (k-split: 2 threads per cell,
// interleaved 16B k-chunks, combined with one shfl.bfly per gate).
// 16 warps/SM = 4/SMSP for latency hiding. W_hh in smem (loaded once),
// c in register. Two-group release/acquire grid barrier per step.
// ---------------------------------------------------------------------------
__device__ __forceinline__ float sigmoidf_(float x) { return 1.f / (1.f + expf(-x)); }

__global__ __launch_bounds__(LTHREADS, 1) void lstm_kernel(
    const float* __restrict__ Whh,   // [4H][H] for this layer
    const float* __restrict__ h0,    // [B][H]
    const float* __restrict__ c0,    // [B][H]
    const float* __restrict__ xg,    // transposed gates [4H][T*B]
    float* __restrict__ out,         // [T][B][H]
    float* __restrict__ hn,          // [B][H]
    float* __restrict__ cn)          // [B][H]
{
    extern __shared__ float sm[];
    float* h_sm = sm;                        // [32][516]
    float* w_sm = sm + 32 * H_STRIDE;        // [8 j][4 g x 516] stride 2068

    const int tid  = threadIdx.x;
    const int cta  = blockIdx.x;
    const int jb   = cta & 63;       // 64 j-blocks of 8
    const int bb   = cta >> 6;       // 2 b-blocks of 32 -> barrier group
    const int warp = tid >> 5;
    const int lane = tid & 31;
    const int bq   = warp & 3;       // warp b-quad (0..3)
    const int jq   = warp >> 2;      // warp j-pair (0..3)
    const int bo   = lane & 7;       // lane b offset
    const int jp   = (lane >> 3) & 1;// lane j within pair
    const int kh   = lane >> 4;      // lane k-half (0/1) -> bfly 16 partner
    const int bl   = bq * 8 + bo;    // b_local 0..31
    const int jl   = jq * 2 + jp;    // j_local 0..7
    const int j    = jb * 8 + jl;
    const int b    = bb * 32 + bl;
    const int bj   = b * HID + j;

    unsigned int* bar = &g_barG[bb];

    // preload this CTA's W_hh slice: w_sm[jl][g][k], strides bank-padded
    {
        const float4* Wsrc = (const float4*)Whh;
#pragma unroll
        for (int idx = tid; idx < 4096; idx += LTHREADS) {   // float4 units
            int wjl = idx >> 9;
            int rem = idx & 511;
            int g   = rem >> 7;
            int k4  = rem & 127;
            *(float4*)&w_sm[wjl * WJ_STRIDE + g * WG_STRIDE + k4 * 4] =
                Wsrc[(((size_t)(g * HID + jb * 8 + wjl)) * HID >> 2) + k4];
        }
    }

    float c = c0[bj];
    if (kh == 0) __stcg(&g_hbuf[0][bj], h0[bj]);

    // per-gate xg base pointers (transposed layout: coalesced lane->b)
    const float* xi  = xg + (size_t)(0 * HID + j) * MROWS + b;
    const float* xf  = xg + (size_t)(1 * HID + j) * MROWS + b;
    const float* xgp = xg + (size_t)(2 * HID + j) * MROWS + b;
    const float* xo  = xg + (size_t)(3 * HID + j) * MROWS + b;

    // k-chunk interleave: thread kh handles chunks {2i + kh}, i = 0..63
    const ulonglong2* hp = (const ulonglong2*)&h_sm[bl * H_STRIDE] + kh;
    const ulonglong2* W0 = (const ulonglong2*)&w_sm[jl * WJ_STRIDE + 0 * WG_STRIDE] + kh;
    const ulonglong2* W1 = (const ulonglong2*)&w_sm[jl * WJ_STRIDE + 1 * WG_STRIDE] + kh;
    const ulonglong2* W2 = (const ulonglong2*)&w_sm[jl * WJ_STRIDE + 2 * WG_STRIDE] + kh;
    const ulonglong2* W3 = (const ulonglong2*)&w_sm[jl * WJ_STRIDE + 3 * WG_STRIDE] + kh;

    // initial barrier: h0 writes of this group visible before step 0
    unsigned expect = 0;
    __syncthreads();
    if (tid == 0) {
        red_release_add(bar, 1u);
        expect += NGRP;
        while (ld_acquire(bar) < expect) { }
    }
    __syncthreads();

    // prefetch step-0 gate biases
    float vxi = __ldg(xi), vxf = __ldg(xf), vxg = __ldg(xgp), vxo = __ldg(xo);

    float h = 0.f;
    for (int t = 0; t < TS; t++) {
        const float* hcur = g_hbuf[t & 1];
        // stage this group's 32-batch h slice into smem (L2, coalesced)
#pragma unroll
        for (int idx = tid; idx < 32 * 128; idx += LTHREADS) {
            int r  = idx >> 7;
            int c4 = idx & 127;
            float4 v = __ldcg((const float4*)(hcur + (size_t)(bb * 32 + r) * HID) + c4);
            *(float4*)&h_sm[r * H_STRIDE + c4 * 4] = v;
        }
        __syncthreads();

        unsigned long long ai2 = 0ull, af2 = 0ull, ag2 = 0ull, ao2 = 0ull;
#pragma unroll 8
        for (int i = 0; i < 64; i++) {
            ulonglong2 hv = hp[2 * i];
            ulonglong2 w0 = W0[2 * i], w1 = W1[2 * i], w2 = W2[2 * i], w3 = W3[2 * i];
            ai2 = fma2(hv.x, w0.x, ai2); ai2 = fma2(hv.y, w0.y, ai2);
            af2 = fma2(hv.x, w1.x, af2); af2 = fma2(hv.y, w1.y, af2);
            ag2 = fma2(hv.x, w2.x, ag2); ag2 = fma2(hv.y, w2.y, ag2);
            ao2 = fma2(hv.x, w3.x, ao2); ao2 = fma2(hv.y, w3.y, ao2);
        }

        float2 pi = unpack2(ai2); float2 pf = unpack2(af2);
        float2 pg = unpack2(ag2); float2 po = unpack2(ao2);
        float ri = pi.x + pi.y, rf = pf.x + pf.y;
        float rg = pg.x + pg.y, ro = po.x + po.y;
        // combine the two k-halves (partner lane = lane ^ 16)
        ri += __shfl_xor_sync(0xffffffffu, ri, 16);
        rf += __shfl_xor_sync(0xffffffffu, rf, 16);
        rg += __shfl_xor_sync(0xffffffffu, rg, 16);
        ro += __shfl_xor_sync(0xffffffffu, ro, 16);

        float ig = sigmoidf_(ri + vxi);
        float fg = sigmoidf_(rf + vxf);
        float gg = tanhf(rg + vxg);
        float og = sigmoidf_(ro + vxo);
        c = fg * c + ig * gg;
        h = og * tanhf(c);

        // publish h for step t+1, then arrive (release orders the stcg)
        if (kh == 0) __stcg(&g_hbuf[(t + 1) & 1][bj], h);
        __syncthreads();
        if (tid == 0) {
            red_release_add(bar, 1u);
            expect += NGRP;
        }

        // overlap with barrier wait: out[] DRAM store + next-step xg prefetch
        if (kh == 0) out[((size_t)t * BS + b) * HID + j] = h;
        if (t + 1 < TS) {
            int toff = (t + 1) * BS;
            vxi = __ldg(xi + toff);
            vxf = __ldg(xf + toff);
            vxg = __ldg(xgp + toff);
            vxo = __ldg(xo + toff);
        }

        if (tid == 0) {
            while (ld_acquire(bar) < expect) { }
        }
        __syncthreads();
    }

    if (kh == 0) {
        hn[bj] = h;
        cn[bj] = c;
    }
}

// ---------------------------------------------------------------------------
// Launch: per layer {gemm (resets barrier) -> persistent recurrence}.
// Output layout: [layer_out (T,B,H)][h_n (L,B,H)][c_n (L,B,H)]
// ---------------------------------------------------------------------------
extern "C" void kernel_launch(void* const* d_in, const int* in_sizes, int n_in,
                              void* d_out, int out_size)
{
    const float* x    = (const float*)d_in[0];
    const float* h0   = (const float*)d_in[1];
    const float* c0   = (const float*)d_in[2];
    const float* W_ih = (const float*)d_in[3];
    const float* W_hh = (const float*)d_in[4];
    const float* b_ih = (const float*)d_in[5];
    const float* b_hh = (const float*)d_in[6];
    float* out = (float*)d_out;

    cudaFuncSetAttribute(lstm_kernel, cudaFuncAttributeMaxDynamicSharedMemorySize, LSTM_SMEM);

    void* p_out1_v = nullptr;
    cudaGetSymbolAddress(&p_out1_v, g_out1);
    float* p_out1 = (float*)p_out1_v;
    void* p_xg_v = nullptr;
    cudaGetSymbolAddress(&p_xg_v, g_xgates);
    const float* p_xg = (const float*)p_xg_v;

    dim3 ggrid(G4 / 128, MROWS / 128);   // (16, 512)

    // Layer 0
    gemm_xg<<<ggrid, 256>>>(x, W_ih, b_ih, b_hh);
    lstm_kernel<<<NCTA, LTHREADS, LSTM_SMEM>>>(
        W_hh, h0, c0, p_xg,
        p_out1,
        out + TBH,                       // h_n[0]
        out + TBH + 2 * (size_t)BH);     // c_n[0]

    // Layer 1
    gemm_xg<<<ggrid, 256>>>(p_out1, W_ih + (size_t)G4 * HID, b_ih + G4, b_hh + G4);
    lstm_kernel<<<NCTA, LTHREADS, LSTM_SMEM>>>(
        W_hh + (size_t)G4 * HID, h0 + BH, c0 + BH, p_xg,
        out,                             // final layer_out
        out + TBH + (size_t)BH,          // h_n[1]
        out + TBH + 3 * (size_t)BH);     // c_n[1]

    (void)in_sizes; (void)n_in; (void)out_size;
}

// round 8
// speedup vs baseline: 1.3733x; 1.3732x over previous
#include <cuda_runtime.h>
#include <math.h>

#define TS   1024
#define BS   64
#define HID  512
#define G4   2048
#define NCTA 128
#define NGRP 64
#define LTHREADS 512
#define MROWS 65536
#define TBH  ((size_t)TS * BS * HID)
#define BH   (BS * HID)

// lstm smem (floats): W [8j][4g*512+pad] + partial buffer
#define WJ_STRIDE 2052               // 513 f4 == 1 mod 8 -> 8-j LDS conflict-free
#define WG_STRIDE 512
#define P_OFF     (8 * WJ_STRIDE)    // 16416 floats
#define SEG_F4    88                 // per (kq,g) segment, f4 units (2*44)
#define BH_F4     44                 // bh sub-stride (44 f4: *4=176 floats ==16 mod 32)
#define P_FLOATS  (32 * SEG_F4 * 4)  // 11264
#define LSTM_SMEM ((P_OFF + P_FLOATS) * 4)   // 110720 bytes

__device__ float g_xgates[(size_t)G4 * MROWS];   // transposed [col][row]
__device__ float g_out1[(size_t)TS * BS * HID];
__device__ float g_hbufT[2][HID * BS];           // TRANSPOSED h: [k][b]
__device__ unsigned int g_barG[2];

__device__ __forceinline__ unsigned long long fma2(unsigned long long a,
                                                   unsigned long long b,
                                                   unsigned long long c) {
    unsigned long long d;
    asm("fma.rn.f32x2 %0, %1, %2, %3;" : "=l"(d) : "l"(a), "l"(b), "l"(c));
    return d;
}
__device__ __forceinline__ unsigned long long pack2(float x, float y) {
    unsigned long long d;
    asm("mov.b64 %0, {%1, %2};" : "=l"(d) : "f"(x), "f"(y));
    return d;
}
__device__ __forceinline__ float2 unpack2(unsigned long long v) {
    float2 r;
    asm("mov.b64 {%0, %1}, %2;" : "=f"(r.x), "=f"(r.y) : "l"(v));
    return r;
}
__device__ __forceinline__ void red_release_add(unsigned int* p, unsigned int v) {
    asm volatile("red.release.gpu.global.add.u32 [%0], %1;" :: "l"(p), "r"(v) : "memory");
}
__device__ __forceinline__ unsigned int ld_acquire(const unsigned int* p) {
    unsigned int v;
    asm volatile("ld.acquire.gpu.global.u32 %0, [%1];" : "=r"(v) : "l"(p) : "memory");
    return v;
}
__device__ __forceinline__ float sigmoidf_(float x) { return 1.f / (1.f + expf(-x)); }

// ---------------- input projection GEMM (unchanged; resets barrier) --------
__global__ __launch_bounds__(256, 2) void gemm_xg(
    const float* __restrict__ A, const float* __restrict__ W,
    const float* __restrict__ b1, const float* __restrict__ b2)
{
    if (blockIdx.x == 0 && blockIdx.y == 0 && threadIdx.x == 0) {
        g_barG[0] = 0u; g_barG[1] = 0u;
    }
    __shared__ float As[16][128];
    __shared__ float Bs[16][128];
    const int tid = threadIdx.x;
    const int m0 = blockIdx.y * 128, n0 = blockIdx.x * 128;
    const int tx = tid & 15, ty = tid >> 4;
    const int lr = tid >> 2, lk = (tid & 3) << 2;
    const float* Ap = A + (size_t)(m0 + lr) * HID + lk;
    const float* Wp = W + (size_t)(n0 + lr) * HID + lk;

    unsigned long long acc2[8][4];
#pragma unroll
    for (int i = 0; i < 8; i++)
#pragma unroll
        for (int j = 0; j < 4; j++) acc2[i][j] = 0ull;

    for (int k0 = 0; k0 < HID; k0 += 16) {
        float4 a0 = *(const float4*)(Ap + k0);
        float4 a1 = *(const float4*)(Ap + (size_t)64 * HID + k0);
        float4 w0 = *(const float4*)(Wp + k0);
        float4 w1 = *(const float4*)(Wp + (size_t)64 * HID + k0);
        __syncthreads();
        As[lk + 0][lr] = a0.x; As[lk + 1][lr] = a0.y; As[lk + 2][lr] = a0.z; As[lk + 3][lr] = a0.w;
        As[lk + 0][lr + 64] = a1.x; As[lk + 1][lr + 64] = a1.y; As[lk + 2][lr + 64] = a1.z; As[lk + 3][lr + 64] = a1.w;
        Bs[lk + 0][lr] = w0.x; Bs[lk + 1][lr] = w0.y; Bs[lk + 2][lr] = w0.z; Bs[lk + 3][lr] = w0.w;
        Bs[lk + 0][lr + 64] = w1.x; Bs[lk + 1][lr + 64] = w1.y; Bs[lk + 2][lr + 64] = w1.z; Bs[lk + 3][lr + 64] = w1.w;
        __syncthreads();
#pragma unroll
        for (int k = 0; k < 16; k++) {
            float a[8];
            *(float4*)&a[0] = *(const float4*)&As[k][ty * 8];
            *(float4*)&a[4] = *(const float4*)&As[k][ty * 8 + 4];
            const ulonglong2* bp = (const ulonglong2*)&Bs[k][tx * 8];
            ulonglong2 t0 = bp[0], t1 = bp[1];
#pragma unroll
            for (int i = 0; i < 8; i++) {
                unsigned long long ad = pack2(a[i], a[i]);
                acc2[i][0] = fma2(ad, t0.x, acc2[i][0]);
                acc2[i][1] = fma2(ad, t0.y, acc2[i][1]);
                acc2[i][2] = fma2(ad, t1.x, acc2[i][2]);
                acc2[i][3] = fma2(ad, t1.y, acc2[i][3]);
            }
        }
    }
    float val[8][8];
#pragma unroll
    for (int i = 0; i < 8; i++)
#pragma unroll
        for (int jp = 0; jp < 4; jp++) {
            float2 p = unpack2(acc2[i][jp]);
            val[i][2 * jp] = p.x; val[i][2 * jp + 1] = p.y;
        }
#pragma unroll
    for (int u = 0; u < 8; u++) {
        int col = n0 + tx * 8 + u;
        float bias = b1[col] + b2[col];
        float* Cp = g_xgates + (size_t)col * MROWS + m0 + ty * 8;
        float4 lo, hi;
        lo.x = val[0][u] + bias; lo.y = val[1][u] + bias;
        lo.z = val[2][u] + bias; lo.w = val[3][u] + bias;
        hi.x = val[4][u] + bias; hi.y = val[5][u] + bias;
        hi.z = val[6][u] + bias; hi.w = val[7][u] + bias;
        *(float4*)Cp = lo; *(float4*)(Cp + 4) = hi;
    }
}

// ---------------- persistent recurrence ------------------------------------
__global__ __launch_bounds__(LTHREADS, 1) void lstm_kernel(
    const float* __restrict__ Whh, const float* __restrict__ h0,
    const float* __restrict__ c0, const float* __restrict__ xg,
    float* __restrict__ out, float* __restrict__ hn, float* __restrict__ cn)
{
    extern __shared__ float sm[];
    float* w_sm = sm;                // [8j][4g][512k], j-stride 2052
    float* p_sm = sm + P_OFF;        // partials: 32 segs x 88 f4

    const int tid  = threadIdx.x;
    const int cta  = blockIdx.x;
    const int jb   = cta & 63;
    const int bb   = cta >> 6;
    const int warp = tid >> 5;
    const int lane = tid & 31;
    // dot roles
    const int bh = warp & 1;         // b half (16)
    const int kq = warp >> 1;        // k eighth
    const int bq = lane & 3;         // b quad within half
    const int jl = lane >> 2;        // j 0..7
    const int k0b = kq * 64;
    // cell roles (tid < 256)
    const int cj = warp;             // j 0..7
    const int cb = lane;             // b 0..31

    unsigned int* bar = &g_barG[bb];

    // preload W_hh slice
    {
        const float4* Wsrc = (const float4*)Whh;
#pragma unroll
        for (int idx = tid; idx < 4096; idx += LTHREADS) {
            int wj = idx >> 9, g = (idx >> 7) & 3, k4 = idx & 127;
            *(float4*)&w_sm[wj * WJ_STRIDE + g * WG_STRIDE + k4 * 4] =
                Wsrc[(((size_t)(g * HID + jb * 8 + wj)) * HID >> 2) + k4];
        }
    }

    float c = 0.f, h = 0.f;
    int jg = 0, bg = 0;
    const float *xp0 = xg, *xp1 = xg, *xp2 = xg, *xp3 = xg;
    if (tid < 256) {
        jg = jb * 8 + cj;
        bg = bb * 32 + cb;
        c = c0[bg * HID + jg];
        __stcg(&g_hbufT[0][jg * BS + bg], h0[(size_t)bg * HID + jg]);
        xp0 = xg + (size_t)(0 * HID + jg) * MROWS + bg;
        xp1 = xg + (size_t)(1 * HID + jg) * MROWS + bg;
        xp2 = xg + (size_t)(2 * HID + jg) * MROWS + bg;
        xp3 = xg + (size_t)(3 * HID + jg) * MROWS + bg;
    }

    // initial barrier (h0 publishes visible)
    unsigned expect = 0;
    __syncthreads();
    if (tid == 0) {
        red_release_add(bar, 1u);
        expect += NGRP;
        while (ld_acquire(bar) < expect) { }
    }
    __syncthreads();

    float vx0 = 0.f, vx1 = 0.f, vx2 = 0.f, vx3 = 0.f;
    if (tid < 256) {
        vx0 = __ldg(xp0); vx1 = __ldg(xp1); vx2 = __ldg(xp2); vx3 = __ldg(xp3);
    }

    // dot pointers
    const int hcol = bb * 32 + bh * 16 + bq * 4;
    const float* wrow = &w_sm[jl * WJ_STRIDE + k0b];
    // partial store base (f4 units)
    const int pst = bh * BH_F4 + jl * 5 + bq;

    for (int t = 0; t < TS; t++) {
        const float* hT = g_hbufT[t & 1] + (size_t)k0b * BS + hcol;

        unsigned long long acc[2][4];
#pragma unroll
        for (int bp = 0; bp < 2; bp++)
#pragma unroll
            for (int g = 0; g < 4; g++) acc[bp][g] = 0ull;

#pragma unroll 2
        for (int ck = 0; ck < 16; ck++) {
            int kb = ck * 4;
            float4 hv0 = __ldcg((const float4*)(hT + (kb + 0) * BS));
            float4 hv1 = __ldcg((const float4*)(hT + (kb + 1) * BS));
            float4 hv2 = __ldcg((const float4*)(hT + (kb + 2) * BS));
            float4 hv3 = __ldcg((const float4*)(hT + (kb + 3) * BS));
            float4 wv0 = *(const float4*)(wrow + 0 * WG_STRIDE + kb);
            float4 wv1 = *(const float4*)(wrow + 1 * WG_STRIDE + kb);
            float4 wv2 = *(const float4*)(wrow + 2 * WG_STRIDE + kb);
            float4 wv3 = *(const float4*)(wrow + 3 * WG_STRIDE + kb);
#pragma unroll
            for (int kk = 0; kk < 4; kk++) {
                float4 hv = (kk == 0) ? hv0 : (kk == 1) ? hv1 : (kk == 2) ? hv2 : hv3;
                unsigned long long hlo = pack2(hv.x, hv.y);
                unsigned long long hhi = pack2(hv.z, hv.w);
                float w0s = (kk == 0) ? wv0.x : (kk == 1) ? wv0.y : (kk == 2) ? wv0.z : wv0.w;
                float w1s = (kk == 0) ? wv1.x : (kk == 1) ? wv1.y : (kk == 2) ? wv1.z : wv1.w;
                float w2s = (kk == 0) ? wv2.x : (kk == 1) ? wv2.y : (kk == 2) ? wv2.z : wv2.w;
                float w3s = (kk == 0) ? wv3.x : (kk == 1) ? wv3.y : (kk == 2) ? wv3.z : wv3.w;
                unsigned long long w0d = pack2(w0s, w0s);
                unsigned long long w1d = pack2(w1s, w1s);
                unsigned long long w2d = pack2(w2s, w2s);
                unsigned long long w3d = pack2(w3s, w3s);
                acc[0][0] = fma2(hlo, w0d, acc[0][0]); acc[1][0] = fma2(hhi, w0d, acc[1][0]);
                acc[0][1] = fma2(hlo, w1d, acc[0][1]); acc[1][1] = fma2(hhi, w1d, acc[1][1]);
                acc[0][2] = fma2(hlo, w2d, acc[0][2]); acc[1][2] = fma2(hhi, w2d, acc[1][2]);
                acc[0][3] = fma2(hlo, w3d, acc[0][3]); acc[1][3] = fma2(hhi, w3d, acc[1][3]);
            }
        }

        // store partials: one STS.128 per gate
#pragma unroll
        for (int g = 0; g < 4; g++) {
            float2 lo = unpack2(acc[0][g]);
            float2 hi = unpack2(acc[1][g]);
            float4 v; v.x = lo.x; v.y = lo.y; v.z = hi.x; v.w = hi.y;
            ((float4*)p_sm)[(kq * 4 + g) * SEG_F4 + pst] = v;
        }
        __syncthreads();

        // cell threads: reduce over kq, activations, publish
        if (tid < 256) {
            int boff = (cb >> 4) * 176 + (cb & 15);
            float r0 = vx0, r1 = vx1, r2 = vx2, r3 = vx3;
#pragma unroll
            for (int q = 0; q < 8; q++) {
                int base = q * 4 * SEG_F4 * 4 + boff + cj * 20;
                r0 += p_sm[base + 0 * SEG_F4 * 4];
                r1 += p_sm[base + 1 * SEG_F4 * 4];
                r2 += p_sm[base + 2 * SEG_F4 * 4];
                r3 += p_sm[base + 3 * SEG_F4 * 4];
            }
            float ig = sigmoidf_(r0);
            float fg = sigmoidf_(r1);
            float gg = tanhf(r2);
            float og = sigmoidf_(r3);
            c = fg * c + ig * gg;
            h = og * tanhf(c);
            __stcg(&g_hbufT[(t + 1) & 1][jg * BS + bg], h);
        }
        __syncthreads();
        if (tid == 0) {
            red_release_add(bar, 1u);
            expect += NGRP;
        }
        // overlap barrier wait: out store + next xg prefetch
        if (tid < 256) {
            out[((size_t)t * BS + bg) * HID + jg] = h;
            if (t + 1 < TS) {
                int toff = (t + 1) * BS;
                vx0 = __ldg(xp0 + toff);
                vx1 = __ldg(xp1 + toff);
                vx2 = __ldg(xp2 + toff);
                vx3 = __ldg(xp3 + toff);
            }
        }
        if (tid == 0) {
            while (ld_acquire(bar) < expect) { }
        }
        __syncthreads();
    }

    if (tid < 256) {
        hn[(size_t)bg * HID + jg] = h;
        cn[(size_t)bg * HID + jg] = c;
    }
}

// ---------------- launch ----------------------------------------------------
extern "C" void kernel_launch(void* const* d_in, const int* in_sizes, int n_in,
                              void* d_out, int out_size)
{
    const float* x    = (const float*)d_in[0];
    const float* h0   = (const float*)d_in[1];
    const float* c0   = (const float*)d_in[2];
    const float* W_ih = (const float*)d_in[3];
    const float* W_hh = (const float*)d_in[4];
    const float* b_ih = (const float*)d_in[5];
    const float* b_hh = (const float*)d_in[6];
    float* out = (float*)d_out;

    cudaFuncSetAttribute(lstm_kernel, cudaFuncAttributeMaxDynamicSharedMemorySize, LSTM_SMEM);

    void* p_out1_v = nullptr;
    cudaGetSymbolAddress(&p_out1_v, g_out1);
    float* p_out1 = (float*)p_out1_v;
    void* p_xg_v = nullptr;
    cudaGetSymbolAddress(&p_xg_v, g_xgates);
    const float* p_xg = (const float*)p_xg_v;

    dim3 ggrid(G4 / 128, MROWS / 128);

    // Layer 0
    gemm_xg<<<ggrid, 256>>>(x, W_ih, b_ih, b_hh);
    lstm_kernel<<<NCTA, LTHREADS, LSTM_SMEM>>>(
        W_hh, h0, c0, p_xg, p_out1,
        out + TBH, out + TBH + 2 * (size_t)BH);

    // Layer 1
    gemm_xg<<<ggrid, 256>>>(p_out1, W_ih + (size_t)G4 * HID, b_ih + G4, b_hh + G4);
    lstm_kernel<<<NCTA, LTHREADS, LSTM_SMEM>>>(
        W_hh + (size_t)G4 * HID, h0 + BH, c0 + BH, p_xg, out,
        out + TBH + (size_t)BH, out + TBH + 3 * (size_t)BH);

    (void)in_sizes; (void)n_in; (void)out_size;
}

// round 10
// speedup vs baseline: 1.6791x; 1.2227x over previous
#include <cuda_runtime.h>
#include <cuda_bf16.h>
#include <math.h>

#define TS   1024
#define BS   64
#define HID  512
#define G4   2048
#define NCTA 128
#define NGRP 64
#define LTHREADS 512
#define MROWS 65536
#define TBH  ((size_t)TS * BS * HID)
#define BH   (BS * HID)

// ---- lstm smem (unchanged) ----
#define WJ_STRIDE 2052
#define WG_STRIDE 512
#define P_OFF     (8 * WJ_STRIDE)
#define SEG_F4    88
#define BH_F4     44
#define P_FLOATS  (32 * SEG_F4 * 4)
#define LSTM_SMEM ((P_OFF + P_FLOATS) * 4)

// ---- mma gemm smem (bf16 units / bytes) ----
#define AS_STRIDE 72                       // bf16 per row (64 + 8 pad)
#define GS_AHI    0
#define GS_ALO    18432
#define GS_BHI    36864
#define GS_BLO    55296
#define GS_BIAS   73728                    // 128 floats
#define GSMEM     (73728 + 512)
#define DS_STRIDE 132                      // epilogue transpose stride (floats)

// Scratch (device globals)
__device__ float g_xgates[(size_t)G4 * MROWS];     // transposed [col][row]
__device__ float g_out1[(size_t)TS * BS * HID];
__device__ float g_hbufT[2][HID * BS];             // transposed h: [k][b]
__device__ unsigned int g_barG[2];
__device__ __nv_bfloat16 g_xhi[(size_t)MROWS * HID];
__device__ __nv_bfloat16 g_xlo[(size_t)MROWS * HID];
__device__ __nv_bfloat16 g_whi[(size_t)G4 * HID];
__device__ __nv_bfloat16 g_wlo[(size_t)G4 * HID];

// ---- packed f32x2 helpers ----
__device__ __forceinline__ unsigned long long fma2(unsigned long long a,
                                                   unsigned long long b,
                                                   unsigned long long c) {
    unsigned long long d;
    asm("fma.rn.f32x2 %0, %1, %2, %3;" : "=l"(d) : "l"(a), "l"(b), "l"(c));
    return d;
}
__device__ __forceinline__ unsigned long long pack2(float x, float y) {
    unsigned long long d;
    asm("mov.b64 %0, {%1, %2};" : "=l"(d) : "f"(x), "f"(y));
    return d;
}
__device__ __forceinline__ float2 unpack2(unsigned long long v) {
    float2 r;
    asm("mov.b64 {%0, %1}, %2;" : "=f"(r.x), "=f"(r.y) : "l"(v));
    return r;
}
__device__ __forceinline__ void red_release_add(unsigned int* p, unsigned int v) {
    asm volatile("red.release.gpu.global.add.u32 [%0], %1;" :: "l"(p), "r"(v) : "memory");
}
__device__ __forceinline__ unsigned int ld_acquire(const unsigned int* p) {
    unsigned int v;
    asm volatile("ld.acquire.gpu.global.u32 %0, [%1];" : "=r"(v) : "l"(p) : "memory");
    return v;
}
__device__ __forceinline__ float sigmoidf_(float x) { return 1.f / (1.f + expf(-x)); }

__device__ __forceinline__ void mma16816(float* d, const unsigned* a, const unsigned* b) {
    asm volatile(
        "mma.sync.aligned.m16n8k16.row.col.f32.bf16.bf16.f32 "
        "{%0,%1,%2,%3}, {%4,%5,%6,%7}, {%8,%9}, {%0,%1,%2,%3};"
        : "+f"(d[0]), "+f"(d[1]), "+f"(d[2]), "+f"(d[3])
        : "r"(a[0]), "r"(a[1]), "r"(a[2]), "r"(a[3]), "r"(b[0]), "r"(b[1]));
}

// ---------------------------------------------------------------------------
// Split-convert fp32 -> bf16 hi/lo. Optionally resets barrier counters.
// ---------------------------------------------------------------------------
__global__ void convert_split(const float* __restrict__ src,
                              __nv_bfloat16* __restrict__ hi,
                              __nv_bfloat16* __restrict__ lo,
                              size_t n, int reset)
{
    if (reset && blockIdx.x == 0 && threadIdx.x == 0) {
        g_barG[0] = 0u; g_barG[1] = 0u;
    }
    size_t stride = (size_t)gridDim.x * blockDim.x;
    for (size_t i = (size_t)blockIdx.x * blockDim.x + threadIdx.x; i < n; i += stride) {
        float v = src[i];
        __nv_bfloat16 h = __float2bfloat16(v);
        hi[i] = h;
        lo[i] = __float2bfloat16(v - __bfloat162float(h));
    }
}

// ---------------------------------------------------------------------------
// bf16-split projection GEMM via mma.sync (baseline PTX, HMMA fallback).
// C_T[g][m] = x[m,:]·W[g,:] + b1[g] + b2[g]; 3 products hh+hl+lh in fp32.
// CTA tile M=128 x N=128 x K=512, k-blocks of 64; 512 thr = 16 warps of 32x32.
// ---------------------------------------------------------------------------
__global__ __launch_bounds__(512, 1) void gemm_mma(
    const __nv_bfloat16* __restrict__ Ahi, const __nv_bfloat16* __restrict__ Alo,
    const __nv_bfloat16* __restrict__ Bhi, const __nv_bfloat16* __restrict__ Blo,
    const float* __restrict__ b1, const float* __restrict__ b2)
{
    extern __shared__ char smem[];
    __nv_bfloat16* As_hi = (__nv_bfloat16*)(smem + GS_AHI);
    __nv_bfloat16* As_lo = (__nv_bfloat16*)(smem + GS_ALO);
    __nv_bfloat16* Bs_hi = (__nv_bfloat16*)(smem + GS_BHI);
    __nv_bfloat16* Bs_lo = (__nv_bfloat16*)(smem + GS_BLO);
    float* bias_sm = (float*)(smem + GS_BIAS);
    float* Ds = (float*)smem;            // epilogue reuse: 128 x 132 floats

    const int tid  = threadIdx.x;
    const int warp = tid >> 5;
    const int lane = tid & 31;
    const int wm = (warp & 3) * 32;      // warp m offset
    const int wn = (warp >> 2) * 32;     // warp n offset
    const int g0 = blockIdx.x * 128;
    const int m0 = blockIdx.y * 128;

    for (int i = tid; i < 128; i += 512)
        bias_sm[i] = b1[g0 + i] + b2[g0 + i];

    float d[2][4][4];
#pragma unroll
    for (int fi = 0; fi < 2; fi++)
#pragma unroll
        for (int fj = 0; fj < 4; fj++)
#pragma unroll
            for (int r = 0; r < 4; r++) d[fi][fj][r] = 0.f;

    const int lr = lane >> 2;            // 0..7
    const int lc = lane & 3;             // 0..3

    for (int kb = 0; kb < 8; kb++) {
        const int k0 = kb * 64;
        __syncthreads();
        // stage k-block: A rows = x[m0..+128], B rows = W[g0..+128]
#pragma unroll
        for (int idx = tid; idx < 1024; idx += 512) {
            int row = idx >> 3, c = idx & 7;
            size_t asrc = (size_t)(m0 + row) * HID + k0 + c * 8;
            size_t bsrc = (size_t)(g0 + row) * HID + k0 + c * 8;
            int doff = row * AS_STRIDE + c * 8;
            *(float4*)(As_hi + doff) = *(const float4*)(Ahi + asrc);
            *(float4*)(As_lo + doff) = *(const float4*)(Alo + asrc);
            *(float4*)(Bs_hi + doff) = *(const float4*)(Bhi + bsrc);
            *(float4*)(Bs_lo + doff) = *(const float4*)(Blo + bsrc);
        }
        __syncthreads();

#pragma unroll
        for (int ks = 0; ks < 4; ks++) {
            const int kc = ks * 16 + lc * 2;
            unsigned ah[2][4], al[2][4];
#pragma unroll
            for (int fi = 0; fi < 2; fi++) {
                int base = (wm + fi * 16 + lr) * AS_STRIDE;
                ah[fi][0] = *(const unsigned*)(As_hi + base + kc);
                ah[fi][1] = *(const unsigned*)(As_hi + base + 8 * AS_STRIDE + kc);
                ah[fi][2] = *(const unsigned*)(As_hi + base + kc + 8);
                ah[fi][3] = *(const unsigned*)(As_hi + base + 8 * AS_STRIDE + kc + 8);
                al[fi][0] = *(const unsigned*)(As_lo + base + kc);
                al[fi][1] = *(const unsigned*)(As_lo + base + 8 * AS_STRIDE + kc);
                al[fi][2] = *(const unsigned*)(As_lo + base + kc + 8);
                al[fi][3] = *(const unsigned*)(As_lo + base + 8 * AS_STRIDE + kc + 8);
            }
            unsigned bh[4][2], bl[4][2];
#pragma unroll
            for (int fj = 0; fj < 4; fj++) {
                int base = (wn + fj * 8 + lr) * AS_STRIDE;
                bh[fj][0] = *(const unsigned*)(Bs_hi + base + kc);
                bh[fj][1] = *(const unsigned*)(Bs_hi + base + kc + 8);
                bl[fj][0] = *(const unsigned*)(Bs_lo + base + kc);
                bl[fj][1] = *(const unsigned*)(Bs_lo + base + kc + 8);
            }
#pragma unroll
            for (int fi = 0; fi < 2; fi++)
#pragma unroll
                for (int fj = 0; fj < 4; fj++) {
                    mma16816(d[fi][fj], ah[fi], bh[fj]);   // hi x hi
                    mma16816(d[fi][fj], ah[fi], bl[fj]);   // hi x lo
                    mma16816(d[fi][fj], al[fi], bh[fj]);   // lo x hi
                }
        }
    }

    // epilogue: transpose through smem, coalesced store with bias
    __syncthreads();
#pragma unroll
    for (int fi = 0; fi < 2; fi++)
#pragma unroll
        for (int fj = 0; fj < 4; fj++) {
            int r = wm + fi * 16 + lr;
            int c = wn + fj * 8 + lc * 2;
            Ds[(c + 0) * DS_STRIDE + r]     = d[fi][fj][0];
            Ds[(c + 1) * DS_STRIDE + r]     = d[fi][fj][1];
            Ds[(c + 0) * DS_STRIDE + r + 8] = d[fi][fj][2];
            Ds[(c + 1) * DS_STRIDE + r + 8] = d[fi][fj][3];
        }
    __syncthreads();
#pragma unroll
    for (int idx = tid; idx < 128 * 32; idx += 512) {
        int col = idx >> 5, ch = idx & 31;
        float4 v = *(const float4*)(Ds + col * DS_STRIDE + ch * 4);
        float b = bias_sm[col];
        v.x += b; v.y += b; v.z += b; v.w += b;
        *(float4*)(g_xgates + (size_t)(g0 + col) * MROWS + m0 + ch * 4) = v;
    }
}

// ---------------------------------------------------------------------------
// Persistent recurrence (byte-identical to round 8)
// ---------------------------------------------------------------------------
__global__ __launch_bounds__(LTHREADS, 1) void lstm_kernel(
    const float* __restrict__ Whh, const float* __restrict__ h0,
    const float* __restrict__ c0, const float* __restrict__ xg,
    float* __restrict__ out, float* __restrict__ hn, float* __restrict__ cn)
{
    extern __shared__ float sm[];
    float* w_sm = sm;
    float* p_sm = sm + P_OFF;

    const int tid  = threadIdx.x;
    const int cta  = blockIdx.x;
    const int jb   = cta & 63;
    const int bb   = cta >> 6;
    const int warp = tid >> 5;
    const int lane = tid & 31;
    const int bh = warp & 1;
    const int kq = warp >> 1;
    const int bq = lane & 3;
    const int jl = lane >> 2;
    const int k0b = kq * 64;
    const int cj = warp;
    const int cb = lane;

    unsigned int* bar = &g_barG[bb];

    {
        const float4* Wsrc = (const float4*)Whh;
#pragma unroll
        for (int idx = tid; idx < 4096; idx += LTHREADS) {
            int wj = idx >> 9, g = (idx >> 7) & 3, k4 = idx & 127;
            *(float4*)&w_sm[wj * WJ_STRIDE + g * WG_STRIDE + k4 * 4] =
                Wsrc[(((size_t)(g * HID + jb * 8 + wj)) * HID >> 2) + k4];
        }
    }

    float c = 0.f, h = 0.f;
    int jg = 0, bg = 0;
    const float *xp0 = xg, *xp1 = xg, *xp2 = xg, *xp3 = xg;
    if (tid < 256) {
        jg = jb * 8 + cj;
        bg = bb * 32 + cb;
        c = c0[bg * HID + jg];
        __stcg(&g_hbufT[0][jg * BS + bg], h0[(size_t)bg * HID + jg]);
        xp0 = xg + (size_t)(0 * HID + jg) * MROWS + bg;
        xp1 = xg + (size_t)(1 * HID + jg) * MROWS + bg;
        xp2 = xg + (size_t)(2 * HID + jg) * MROWS + bg;
        xp3 = xg + (size_t)(3 * HID + jg) * MROWS + bg;
    }

    unsigned expect = 0;
    __syncthreads();
    if (tid == 0) {
        red_release_add(bar, 1u);
        expect += NGRP;
        while (ld_acquire(bar) < expect) { }
    }
    __syncthreads();

    float vx0 = 0.f, vx1 = 0.f, vx2 = 0.f, vx3 = 0.f;
    if (tid < 256) {
        vx0 = __ldg(xp0); vx1 = __ldg(xp1); vx2 = __ldg(xp2); vx3 = __ldg(xp3);
    }

    const int hcol = bb * 32 + bh * 16 + bq * 4;
    const float* wrow = &w_sm[jl * WJ_STRIDE + k0b];
    const int pst = bh * BH_F4 + jl * 5 + bq;

    for (int t = 0; t < TS; t++) {
        const float* hT = g_hbufT[t & 1] + (size_t)k0b * BS + hcol;

        unsigned long long acc[2][4];
#pragma unroll
        for (int bp = 0; bp < 2; bp++)
#pragma unroll
            for (int g = 0; g < 4; g++) acc[bp][g] = 0ull;

#pragma unroll 2
        for (int ck = 0; ck < 16; ck++) {
            int kb = ck * 4;
            float4 hv0 = __ldcg((const float4*)(hT + (kb + 0) * BS));
            float4 hv1 = __ldcg((const float4*)(hT + (kb + 1) * BS));
            float4 hv2 = __ldcg((const float4*)(hT + (kb + 2) * BS));
            float4 hv3 = __ldcg((const float4*)(hT + (kb + 3) * BS));
            float4 wv0 = *(const float4*)(wrow + 0 * WG_STRIDE + kb);
            float4 wv1 = *(const float4*)(wrow + 1 * WG_STRIDE + kb);
            float4 wv2 = *(const float4*)(wrow + 2 * WG_STRIDE + kb);
            float4 wv3 = *(const float4*)(wrow + 3 * WG_STRIDE + kb);
#pragma unroll
            for (int kk = 0; kk < 4; kk++) {
                float4 hv = (kk == 0) ? hv0 : (kk == 1) ? hv1 : (kk == 2) ? hv2 : hv3;
                unsigned long long hlo = pack2(hv.x, hv.y);
                unsigned long long hhi = pack2(hv.z, hv.w);
                float w0s = (kk == 0) ? wv0.x : (kk == 1) ? wv0.y : (kk == 2) ? wv0.z : wv0.w;
                float w1s = (kk == 0) ? wv1.x : (kk == 1) ? wv1.y : (kk == 2) ? wv1.z : wv1.w;
                float w2s = (kk == 0) ? wv2.x : (kk == 1) ? wv2.y : (kk == 2) ? wv2.z : wv2.w;
                float w3s = (kk == 0) ? wv3.x : (kk == 1) ? wv3.y : (kk == 2) ? wv3.z : wv3.w;
                unsigned long long w0d = pack2(w0s, w0s);
                unsigned long long w1d = pack2(w1s, w1s);
                unsigned long long w2d = pack2(w2s, w2s);
                unsigned long long w3d = pack2(w3s, w3s);
                acc[0][0] = fma2(hlo, w0d, acc[0][0]); acc[1][0] = fma2(hhi, w0d, acc[1][0]);
                acc[0][1] = fma2(hlo, w1d, acc[0][1]); acc[1][1] = fma2(hhi, w1d, acc[1][1]);
                acc[0][2] = fma2(hlo, w2d, acc[0][2]); acc[1][2] = fma2(hhi, w2d, acc[1][2]);
                acc[0][3] = fma2(hlo, w3d, acc[0][3]); acc[1][3] = fma2(hhi, w3d, acc[1][3]);
            }
        }

#pragma unroll
        for (int g = 0; g < 4; g++) {
            float2 lo = unpack2(acc[0][g]);
            float2 hi = unpack2(acc[1][g]);
            float4 v; v.x = lo.x; v.y = lo.y; v.z = hi.x; v.w = hi.y;
            ((float4*)p_sm)[(kq * 4 + g) * SEG_F4 + pst] = v;
        }
        __syncthreads();

        if (tid < 256) {
            int boff = (cb >> 4) * 176 + (cb & 15);
            float r0 = vx0, r1 = vx1, r2 = vx2, r3 = vx3;
#pragma unroll
            for (int q = 0; q < 8; q++) {
                int base = q * 4 * SEG_F4 * 4 + boff + cj * 20;
                r0 += p_sm[base + 0 * SEG_F4 * 4];
                r1 += p_sm[base + 1 * SEG_F4 * 4];
                r2 += p_sm[base + 2 * SEG_F4 * 4];
                r3 += p_sm[base + 3 * SEG_F4 * 4];
            }
            float ig = sigmoidf_(r0);
            float fg = sigmoidf_(r1);
            float gg = tanhf(r2);
            float og = sigmoidf_(r3);
            c = fg * c + ig * gg;
            h = og * tanhf(c);
            __stcg(&g_hbufT[(t + 1) & 1][jg * BS + bg], h);
        }
        __syncthreads();
        if (tid == 0) {
            red_release_add(bar, 1u);
            expect += NGRP;
        }
        if (tid < 256) {
            out[((size_t)t * BS + bg) * HID + jg] = h;
            if (t + 1 < TS) {
                int toff = (t + 1) * BS;
                vx0 = __ldg(xp0 + toff);
                vx1 = __ldg(xp1 + toff);
                vx2 = __ldg(xp2 + toff);
                vx3 = __ldg(xp3 + toff);
            }
        }
        if (tid == 0) {
            while (ld_acquire(bar) < expect) { }
        }
        __syncthreads();
    }

    if (tid < 256) {
        hn[(size_t)bg * HID + jg] = h;
        cn[(size_t)bg * HID + jg] = c;
    }
}

// ---------------- launch ----------------------------------------------------
extern "C" void kernel_launch(void* const* d_in, const int* in_sizes, int n_in,
                              void* d_out, int out_size)
{
    const float* x    = (const float*)d_in[0];
    const float* h0   = (const float*)d_in[1];
    const float* c0   = (const float*)d_in[2];
    const float* W_ih = (const float*)d_in[3];
    const float* W_hh = (const float*)d_in[4];
    const float* b_ih = (const float*)d_in[5];
    const float* b_hh = (const float*)d_in[6];
    float* out = (float*)d_out;

    cudaFuncSetAttribute(lstm_kernel, cudaFuncAttributeMaxDynamicSharedMemorySize, LSTM_SMEM);
    cudaFuncSetAttribute(gemm_mma, cudaFuncAttributeMaxDynamicSharedMemorySize, GSMEM);

    void* pv;
    cudaGetSymbolAddress(&pv, g_out1);  float* p_out1 = (float*)pv;
    cudaGetSymbolAddress(&pv, g_xgates); const float* p_xg = (const float*)pv;
    cudaGetSymbolAddress(&pv, g_xhi);   __nv_bfloat16* p_xhi = (__nv_bfloat16*)pv;
    cudaGetSymbolAddress(&pv, g_xlo);   __nv_bfloat16* p_xlo = (__nv_bfloat16*)pv;
    cudaGetSymbolAddress(&pv, g_whi);   __nv_bfloat16* p_whi = (__nv_bfloat16*)pv;
    cudaGetSymbolAddress(&pv, g_wlo);   __nv_bfloat16* p_wlo = (__nv_bfloat16*)pv;

    dim3 ggrid(G4 / 128, MROWS / 128);   // (16, 512)

    // Layer 0
    convert_split<<<2048, 256>>>(x, p_xhi, p_xlo, (size_t)MROWS * HID, 1);
    convert_split<<<256, 256>>>(W_ih, p_whi, p_wlo, (size_t)G4 * HID, 0);
    gemm_mma<<<ggrid, 512, GSMEM>>>(p_xhi, p_xlo, p_whi, p_wlo, b_ih, b_hh);
    lstm_kernel<<<NCTA, LTHREADS, LSTM_SMEM>>>(
        W_hh, h0, c0, p_xg, p_out1,
        out + TBH, out + TBH + 2 * (size_t)BH);

    // Layer 1
    convert_split<<<2048, 256>>>(p_out1, p_xhi, p_xlo, (size_t)MROWS * HID, 1);
    convert_split<<<256, 256>>>(W_ih + (size_t)G4 * HID, p_whi, p_wlo, (size_t)G4 * HID, 0);
    gemm_mma<<<ggrid, 512, GSMEM>>>(p_xhi, p_xlo, p_whi, p_wlo, b_ih + G4, b_hh + G4);
    lstm_kernel<<<NCTA, LTHREADS, LSTM_SMEM>>>(
        W_hh + (size_t)G4 * HID, h0 + BH, c0 + BH, p_xg, out,
        out + TBH + (size_t)BH, out + TBH + 3 * (size_t)BH);

    (void)in_sizes; (void)n_in; (void)out_size;
}